// round 9
// baseline (speedup 1.0000x reference)
#include <cuda_runtime.h>
#include <cuda_bf16.h>
#include <math.h>
#include <stdint.h>

// Problem dims
#define QL 2048
#define CTX 2048
#define HDIM 4096
#define NH 32
#define NKV 8
#define HD 128
#define KVLEN (CTX + QL)          // 4096
#define KVSTRIDE (KVLEN * HD)     // elements per kv head

#define QSCALE (0.08838834764831845f * 1.4426950408889634f)   // (1/sqrt(128))*log2(e)

// ---------------------------------------------------------------------------
// Scratch (__device__ globals; allocation-free rule)
// ---------------------------------------------------------------------------
__device__ float g_Q[(size_t)QL * HDIM];
__device__ float g_K[(size_t)NKV * KVLEN * HD];

__device__ __nv_bfloat16 g_hidHi[(size_t)QL * HDIM],  g_hidLo[(size_t)QL * HDIM];
__device__ __nv_bfloat16 g_tgtHi[(size_t)CTX * HDIM], g_tgtLo[(size_t)CTX * HDIM];
__device__ __nv_bfloat16 g_WqHi[(size_t)HDIM * HDIM], g_WqLo[(size_t)HDIM * HDIM];
__device__ __nv_bfloat16 g_WkHi[(size_t)NKV * HD * HDIM], g_WkLo[(size_t)NKV * HD * HDIM];
__device__ __nv_bfloat16 g_WvHi[(size_t)NKV * HD * HDIM], g_WvLo[(size_t)NKV * HD * HDIM];
__device__ __nv_bfloat16 g_WoHi[(size_t)HDIM * HDIM], g_WoLo[(size_t)HDIM * HDIM];
__device__ __nv_bfloat16 g_AHi[(size_t)QL * HDIM],  g_ALo[(size_t)QL * HDIM];

__device__ __nv_bfloat16 g_Qh[(size_t)QL * HDIM],  g_Ql[(size_t)QL * HDIM];
__device__ __nv_bfloat16 g_Kh[(size_t)NKV * KVLEN * HD], g_Kl[(size_t)NKV * KVLEN * HD];
__device__ __nv_bfloat16 g_Vh[(size_t)NKV * KVLEN * HD], g_Vl[(size_t)NKV * KVLEN * HD];

// ---------------------------------------------------------------------------
// PTX helpers (base sm_103-legal only: cp.async, ldmatrix, mma.sync)
// ---------------------------------------------------------------------------
__device__ __forceinline__ uint32_t smem_u32(const void* p) {
    uint32_t a;
    asm("{ .reg .u64 t; cvta.to.shared.u64 t, %1; cvt.u32.u64 %0, t; }" : "=r"(a) : "l"(p));
    return a;
}
#define CP_ASYNC16(dst, src) \
    asm volatile("cp.async.cg.shared.global [%0], [%1], 16;" :: "r"(dst), "l"(src))
#define CP_COMMIT() asm volatile("cp.async.commit_group;" ::: "memory")
#define CP_WAIT1()  asm volatile("cp.async.wait_group 1;" ::: "memory")

#define LDSM_X4(r0, r1, r2, r3, addr) \
    asm volatile("ldmatrix.sync.aligned.m8n8.x4.shared.b16 {%0,%1,%2,%3}, [%4];" \
                 : "=r"(r0), "=r"(r1), "=r"(r2), "=r"(r3) : "r"(addr))
#define LDSM_X4_T(r0, r1, r2, r3, addr) \
    asm volatile("ldmatrix.sync.aligned.m8n8.x4.trans.shared.b16 {%0,%1,%2,%3}, [%4];" \
                 : "=r"(r0), "=r"(r1), "=r"(r2), "=r"(r3) : "r"(addr))

#define MMA16816(d, a, b) \
    asm volatile("mma.sync.aligned.m16n8k16.row.col.f32.bf16.bf16.f32 " \
                 "{%0,%1,%2,%3}, {%4,%5,%6,%7}, {%8,%9}, {%0,%1,%2,%3};" \
                 : "+f"((d)[0]), "+f"((d)[1]), "+f"((d)[2]), "+f"((d)[3]) \
                 : "r"((a)[0]), "r"((a)[1]), "r"((a)[2]), "r"((a)[3]), \
                   "r"((b)[0]), "r"((b)[1]))

#define PACK_BF16X2(r, flo, fhi) \
    asm("cvt.rn.bf16x2.f32 %0, %1, %2;" : "=r"(r) : "f"(fhi), "f"(flo))

// ---------------------------------------------------------------------------
// bf16-split HMMA GEMM v3: 128x256 CTA tile, 512 threads, warp tile 32x64,
// K-chunk 32, 3-stage cp.async pipeline.
// mode 0: C row-major [., ldn]
// mode 1: KV fp32 layout C[head][pos0+row][hd]
// mode 2: V bf16 hi/lo split directly to g_Vh/g_Vl
// ---------------------------------------------------------------------------
#define TM 128
#define TN 256
#define TK 32
#define A_TILE_B (128 * 80)               // 10240 (80B row stride)
#define B_TILE_B (256 * 80)               // 20480
#define OFF_ALO A_TILE_B
#define OFF_BHI (2 * A_TILE_B)
#define OFF_BLO (2 * A_TILE_B + B_TILE_B)
#define STG_B (2 * A_TILE_B + 2 * B_TILE_B)   // 61440
#define SMEM_G (3 * STG_B)                // 184320

__device__ __forceinline__ void g_load_stage(
    uint32_t sb, int stage, int tid,
    const __nv_bfloat16* aHi, const __nv_bfloat16* aLo,
    const __nv_bfloat16* bHi, const __nv_bfloat16* bLo,
    int bm, int bn, int K, int k0)
{
    const uint32_t st = sb + stage * STG_B;
#pragma unroll
    for (int t = 0; t < 6; t++) {
        int idx = tid + 512 * t;          // 0..3071
        const __nv_bfloat16* base;
        int grow, r;
        uint32_t toff;
        if (idx < 512)       { base = aHi; r = idx >> 2;           grow = bm + r; toff = 0; }
        else if (idx < 1024) { base = aLo; r = (idx - 512) >> 2;   grow = bm + r; toff = OFF_ALO; }
        else if (idx < 2048) { base = bHi; r = (idx - 1024) >> 2;  grow = bn + r; toff = OFF_BHI; }
        else                 { base = bLo; r = (idx - 2048) >> 2;  grow = bn + r; toff = OFF_BLO; }
        int c = idx & 3;
        const char* src = (const char*)(base + (size_t)grow * K + k0 + c * 8);
        uint32_t dst = st + toff + r * 80 + c * 16;
        CP_ASYNC16(dst, src);
    }
}

__device__ __forceinline__ void gemm_core(
    const __nv_bfloat16* __restrict__ aHi, const __nv_bfloat16* __restrict__ aLo,
    const __nv_bfloat16* __restrict__ bHi, const __nv_bfloat16* __restrict__ bLo,
    int bm, int bn, int K,
    float* __restrict__ C, int ldn, int mode, int pos0)
{
    extern __shared__ char smem[];
    const uint32_t sb = smem_u32(smem);
    const int tid = threadIdx.x;
    const int wid = tid >> 5;
    const int lane = tid & 31;
    const int wm = (wid >> 2) * 32;       // 4 row groups of 32
    const int wn = (wid & 3) * 64;        // 4 col groups of 64
    const int nch = K / TK;

    float acc[2][8][4];
#pragma unroll
    for (int mt = 0; mt < 2; mt++)
#pragma unroll
        for (int nt = 0; nt < 8; nt++)
#pragma unroll
            for (int i = 0; i < 4; i++) acc[mt][nt][i] = 0.0f;

    g_load_stage(sb, 0, tid, aHi, aLo, bHi, bLo, bm, bn, K, 0);
    CP_COMMIT();
    g_load_stage(sb, 1, tid, aHi, aLo, bHi, bLo, bm, bn, K, TK);
    CP_COMMIT();

    int stage = 0;
    for (int c = 0; c < nch; c++) {
        CP_WAIT1();
        __syncthreads();
        if (c + 2 < nch) {
            int s2 = stage + 2; if (s2 >= 3) s2 -= 3;
            g_load_stage(sb, s2, tid, aHi, aLo, bHi, bLo, bm, bn, K, (c + 2) * TK);
        }
        CP_COMMIT();

        const uint32_t st = sb + stage * STG_B;
#pragma unroll
        for (int kg = 0; kg < 2; kg++) {
            uint32_t ah[2][4], al[2][4];
            const int acol = kg * 16 + (lane >> 4) * 8;
#pragma unroll
            for (int mt = 0; mt < 2; mt++) {
                int row = wm + mt * 16 + (lane & 15);
                uint32_t ad = st + row * 80 + acol * 2;
                LDSM_X4(ah[mt][0], ah[mt][1], ah[mt][2], ah[mt][3], ad);
                LDSM_X4(al[mt][0], al[mt][1], al[mt][2], al[mt][3], ad + OFF_ALO);
            }
            const int bcol = kg * 16 + ((lane >> 3) & 1) * 8;
#pragma unroll
            for (int p = 0; p < 4; p++) {
                uint32_t bh[4], bl[4];
                const int brow = wn + p * 16 + (lane & 7) + (lane >> 4) * 8;
                uint32_t bd = st + OFF_BHI + brow * 80 + bcol * 2;
                LDSM_X4(bh[0], bh[1], bh[2], bh[3], bd);
                LDSM_X4(bl[0], bl[1], bl[2], bl[3], bd + (OFF_BLO - OFF_BHI));
#pragma unroll
                for (int mt = 0; mt < 2; mt++) {
                    MMA16816(acc[mt][2 * p],     ah[mt], &bh[0]);
                    MMA16816(acc[mt][2 * p + 1], ah[mt], &bh[2]);
                    MMA16816(acc[mt][2 * p],     ah[mt], &bl[0]);
                    MMA16816(acc[mt][2 * p + 1], ah[mt], &bl[2]);
                    MMA16816(acc[mt][2 * p],     al[mt], &bh[0]);
                    MMA16816(acc[mt][2 * p + 1], al[mt], &bh[2]);
                }
            }
        }
        stage++; if (stage >= 3) stage = 0;
        __syncthreads();
    }

#pragma unroll
    for (int mt = 0; mt < 2; mt++)
#pragma unroll
        for (int nt = 0; nt < 8; nt++) {
            int row = bm + wm + mt * 16 + (lane >> 2);
            int col = bn + wn + nt * 8 + (lane & 3) * 2;
            if (mode == 0) {
                *(float2*)(C + (size_t)row * ldn + col) =
                    make_float2(acc[mt][nt][0], acc[mt][nt][1]);
                *(float2*)(C + (size_t)(row + 8) * ldn + col) =
                    make_float2(acc[mt][nt][2], acc[mt][nt][3]);
            } else if (mode == 1) {
                const int head = col >> 7;
                const int hd = col & 127;
                float* base = C + (size_t)head * KVSTRIDE + hd;
                *(float2*)(base + (size_t)(pos0 + row) * HD) =
                    make_float2(acc[mt][nt][0], acc[mt][nt][1]);
                *(float2*)(base + (size_t)(pos0 + row + 8) * HD) =
                    make_float2(acc[mt][nt][2], acc[mt][nt][3]);
            } else {
                // V: split to bf16 hi/lo directly
                const int head = col >> 7;
                const int hd = col & 127;
                const size_t e0 = (size_t)head * KVSTRIDE + (size_t)(pos0 + row) * HD + hd;
                const size_t e1 = (size_t)head * KVSTRIDE + (size_t)(pos0 + row + 8) * HD + hd;
                float f0 = acc[mt][nt][0], f1 = acc[mt][nt][1];
                float f2 = acc[mt][nt][2], f3 = acc[mt][nt][3];
                uint32_t h0, h1, l0, l1;
                PACK_BF16X2(h0, f0, f1);
                PACK_BF16X2(h1, f2, f3);
                float r0 = f0 - __uint_as_float(h0 << 16);
                float r1 = f1 - __uint_as_float(h0 & 0xFFFF0000u);
                float r2 = f2 - __uint_as_float(h1 << 16);
                float r3 = f3 - __uint_as_float(h1 & 0xFFFF0000u);
                PACK_BF16X2(l0, r0, r1);
                PACK_BF16X2(l1, r2, r3);
                ((uint32_t*)g_Vh)[e0 >> 1] = h0;
                ((uint32_t*)g_Vl)[e0 >> 1] = l0;
                ((uint32_t*)g_Vh)[e1 >> 1] = h1;
                ((uint32_t*)g_Vl)[e1 >> 1] = l1;
            }
        }
}

// Fused Q + K(ctx,noise) + V(ctx,noise) projections: 512 CTAs, 1D grid.
__global__ __launch_bounds__(512, 1)
void gemm_qkv(float* __restrict__ Qo, float* __restrict__ Ko)
{
    const int cta = blockIdx.x;
    if (cta < 256) {
        const int bm = (cta >> 4) * TM;
        const int bn = (cta & 15) * TN;
        gemm_core(g_hidHi, g_hidLo, g_WqHi, g_WqLo, bm, bn, HDIM, Qo, HDIM, 0, 0);
    } else {
        const int r = cta - 256;
        const int z = r >> 6;
        const int bm = ((r >> 2) & 15) * TM;
        const int bn = (r & 3) * TN;
        const __nv_bfloat16 *aHi, *aLo, *bHi, *bLo;
        int pos0;
        if (z >> 1) { aHi = g_hidHi; aLo = g_hidLo; pos0 = CTX; }
        else        { aHi = g_tgtHi; aLo = g_tgtLo; pos0 = 0; }
        if (z & 1) {
            gemm_core(aHi, aLo, g_WvHi, g_WvLo, bm, bn, HDIM, nullptr, 0, 2, pos0);
        } else {
            gemm_core(aHi, aLo, g_WkHi, g_WkLo, bm, bn, HDIM, Ko, 0, 1, pos0);
        }
    }
}

// Output projection
__global__ __launch_bounds__(512, 1)
void gemm_out(float* __restrict__ C)
{
    const int bm = blockIdx.y * TM;
    const int bn = blockIdx.x * TN;
    gemm_core(g_AHi, g_ALo, g_WoHi, g_WoLo, bm, bn, HDIM, C, HDIM, 0, 0);
}

// ---------------------------------------------------------------------------
// fp32 -> (bf16 hi, bf16 lo) split
// ---------------------------------------------------------------------------
__global__ void cvt_split(const float4* __restrict__ x,
                          __nv_bfloat162* __restrict__ hi,
                          __nv_bfloat162* __restrict__ lo, int n4)
{
    int i = blockIdx.x * blockDim.x + threadIdx.x;
    if (i >= n4) return;
    float4 v = x[i];
    __nv_bfloat16 hx = __float2bfloat16_rn(v.x);
    __nv_bfloat16 hy = __float2bfloat16_rn(v.y);
    __nv_bfloat16 hz = __float2bfloat16_rn(v.z);
    __nv_bfloat16 hw = __float2bfloat16_rn(v.w);
    __nv_bfloat16 lx = __float2bfloat16_rn(v.x - __bfloat162float(hx));
    __nv_bfloat16 ly = __float2bfloat16_rn(v.y - __bfloat162float(hy));
    __nv_bfloat16 lz = __float2bfloat16_rn(v.z - __bfloat162float(hz));
    __nv_bfloat16 lw = __float2bfloat16_rn(v.w - __bfloat162float(hw));
    hi[2 * i + 0] = __halves2bfloat162(hx, hy);
    hi[2 * i + 1] = __halves2bfloat162(hz, hw);
    lo[2 * i + 0] = __halves2bfloat162(lx, ly);
    lo[2 * i + 1] = __halves2bfloat162(lz, lw);
}

// ---------------------------------------------------------------------------
// RoPE -> bf16 hi/lo split outputs (Q folds in scale*log2e)
// ---------------------------------------------------------------------------
__global__ void rope_q_split(const float* __restrict__ Q,
                             const float* __restrict__ cosb,
                             const float* __restrict__ sinb,
                             __nv_bfloat16* __restrict__ qh,
                             __nv_bfloat16* __restrict__ ql)
{
    int idx = blockIdx.x * blockDim.x + threadIdx.x;
    int hd = idx & 63;
    int t  = idx >> 6;
    int h  = t & (NH - 1);
    int s  = t >> 5;
    int pos = CTX + s;
    float c1 = cosb[(size_t)pos * HD + hd];
    float s1 = sinb[(size_t)pos * HD + hd];
    float c2 = cosb[(size_t)pos * HD + hd + 64];
    float s2 = sinb[(size_t)pos * HD + hd + 64];
    const float* p = Q + (size_t)s * HDIM + h * HD;
    float x1 = p[hd];
    float x2 = p[hd + 64];
    float y1 = (x1 * c1 - x2 * s1) * QSCALE;
    float y2 = (x2 * c2 + x1 * s2) * QSCALE;
    size_t o1 = (size_t)s * HDIM + h * HD + hd;
    __nv_bfloat16 h1 = __float2bfloat16_rn(y1);
    __nv_bfloat16 h2 = __float2bfloat16_rn(y2);
    qh[o1]      = h1;  ql[o1]      = __float2bfloat16_rn(y1 - __bfloat162float(h1));
    qh[o1 + 64] = h2;  ql[o1 + 64] = __float2bfloat16_rn(y2 - __bfloat162float(h2));
}

__global__ void rope_k_split(const float* __restrict__ Kb,
                             const float* __restrict__ cosb,
                             const float* __restrict__ sinb,
                             __nv_bfloat16* __restrict__ kh,
                             __nv_bfloat16* __restrict__ kl)
{
    int idx = blockIdx.x * blockDim.x + threadIdx.x;
    int hd = idx & 63;
    int t  = idx >> 6;
    int pos = t & (KVLEN - 1);
    int kvh = t >> 12;
    float c1 = cosb[(size_t)pos * HD + hd];
    float s1 = sinb[(size_t)pos * HD + hd];
    float c2 = cosb[(size_t)pos * HD + hd + 64];
    float s2 = sinb[(size_t)pos * HD + hd + 64];
    const float* p = Kb + (size_t)kvh * KVSTRIDE + (size_t)pos * HD;
    float x1 = p[hd];
    float x2 = p[hd + 64];
    float y1 = x1 * c1 - x2 * s1;
    float y2 = x2 * c2 + x1 * s2;
    size_t o1 = (size_t)kvh * KVSTRIDE + (size_t)pos * HD + hd;
    __nv_bfloat16 h1 = __float2bfloat16_rn(y1);
    __nv_bfloat16 h2 = __float2bfloat16_rn(y2);
    kh[o1]      = h1;  kl[o1]      = __float2bfloat16_rn(y1 - __bfloat162float(h1));
    kh[o1 + 64] = h2;  kl[o1 + 64] = __float2bfloat16_rn(y2 - __bfloat162float(h2));
}

// ---------------------------------------------------------------------------
// Tensor-core flash attention (bf16 3-pass split, mma.sync) — passing version
// ---------------------------------------------------------------------------
#define BQ 128
#define BKV 64
#define RSTR 272
#define SQ_L 34816
#define SSTG 69632
#define STG_SZ 69632
#define T_KH 0
#define T_KL 17408
#define T_VH 34816
#define T_VL 52224
#define ATTN_SMEM (SSTG + 2 * STG_SZ)

__device__ __forceinline__ void attn_load_kv(
    uint32_t sb, int stage, int tid, int kvh, int kc)
{
    const uint32_t st = sb + SSTG + stage * STG_SZ;
    const size_t base = (size_t)kvh * KVSTRIDE + (size_t)kc * BKV * HD;
    const __nv_bfloat16* srcs[4] = { g_Kh + base, g_Kl + base, g_Vh + base, g_Vl + base };
#pragma unroll
    for (int t = 0; t < 16; t++) {
        int idx = tid + 256 * t;
        int tile = idx >> 10;
        int rem = idx & 1023;
        int r = rem >> 4;
        int c = rem & 15;
        const char* src = (const char*)(srcs[tile] + (size_t)r * HD) + c * 16;
        uint32_t dst = st + tile * 17408 + r * RSTR + c * 16;
        CP_ASYNC16(dst, src);
    }
}

__global__ __launch_bounds__(256, 1)
void attn_mma(const __nv_bfloat16* __restrict__ Qh, const __nv_bfloat16* __restrict__ Ql,
              __nv_bfloat16* __restrict__ OHi, __nv_bfloat16* __restrict__ OLo)
{
    extern __shared__ char smem[];
    const uint32_t sb = smem_u32(smem);
    const int tid = threadIdx.x;
    const int wid = tid >> 5;
    const int lane = tid & 31;
    const int h  = blockIdx.y;
    const int q0 = blockIdx.x * BQ;
    const int kvh = h >> 2;

#pragma unroll
    for (int t = 0; t < 16; t++) {
        int idx = tid + 256 * t;
        int tile = idx >> 11;
        int rem = idx & 2047;
        int r = rem >> 4;
        int c = rem & 15;
        const __nv_bfloat16* base = tile ? Ql : Qh;
        const char* src = (const char*)(base + (size_t)(q0 + r) * HDIM + h * HD) + c * 16;
        uint32_t dst = sb + tile * 34816 + r * RSTR + c * 16;
        CP_ASYNC16(dst, src);
    }
    CP_COMMIT();
    attn_load_kv(sb, 0, tid, kvh, 0);
    CP_COMMIT();

    float o[16][4];
#pragma unroll
    for (int nt = 0; nt < 16; nt++)
#pragma unroll
        for (int i = 0; i < 4; i++) o[nt][i] = 0.0f;
    float m0 = -INFINITY, m1 = -INFINITY, l0 = 0.0f, l1 = 0.0f;

    const int NCH = KVLEN / BKV;
    for (int kc = 0; kc < NCH; kc++) {
        if (kc + 1 < NCH) attn_load_kv(sb, (kc + 1) & 1, tid, kvh, kc + 1);
        CP_COMMIT();
        CP_WAIT1();
        __syncthreads();

        const uint32_t st = sb + SSTG + (kc & 1) * STG_SZ;

        float s[8][4];
#pragma unroll
        for (int nt = 0; nt < 8; nt++)
#pragma unroll
            for (int i = 0; i < 4; i++) s[nt][i] = 0.0f;

#pragma unroll
        for (int d16 = 0; d16 < 8; d16++) {
            uint32_t qhf[4], qlf[4];
            const int arow = wid * 16 + (lane & 15);
            const int acol = d16 * 16 + (lane >> 4) * 8;
            uint32_t aaddr = sb + arow * RSTR + acol * 2;
            LDSM_X4(qhf[0], qhf[1], qhf[2], qhf[3], aaddr);
            LDSM_X4(qlf[0], qlf[1], qlf[2], qlf[3], aaddr + SQ_L);
            const int bcol = d16 * 16 + ((lane >> 3) & 1) * 8;
#pragma unroll
            for (int nt2 = 0; nt2 < 4; nt2++) {
                uint32_t bh[4], bl[4];
                const int brow = nt2 * 16 + (lane & 7) + (lane >> 4) * 8;
                uint32_t baddr = st + T_KH + brow * RSTR + bcol * 2;
                LDSM_X4(bh[0], bh[1], bh[2], bh[3], baddr);
                LDSM_X4(bl[0], bl[1], bl[2], bl[3], baddr + (T_KL - T_KH));
                MMA16816(s[2 * nt2],     qhf, &bh[0]);
                MMA16816(s[2 * nt2 + 1], qhf, &bh[2]);
                MMA16816(s[2 * nt2],     qhf, &bl[0]);
                MMA16816(s[2 * nt2 + 1], qhf, &bl[2]);
                MMA16816(s[2 * nt2],     qlf, &bh[0]);
                MMA16816(s[2 * nt2 + 1], qlf, &bh[2]);
            }
        }

        float mloc0 = -INFINITY, mloc1 = -INFINITY;
#pragma unroll
        for (int nt = 0; nt < 8; nt++) {
            mloc0 = fmaxf(mloc0, fmaxf(s[nt][0], s[nt][1]));
            mloc1 = fmaxf(mloc1, fmaxf(s[nt][2], s[nt][3]));
        }
        mloc0 = fmaxf(mloc0, __shfl_xor_sync(0xffffffffu, mloc0, 1));
        mloc0 = fmaxf(mloc0, __shfl_xor_sync(0xffffffffu, mloc0, 2));
        mloc1 = fmaxf(mloc1, __shfl_xor_sync(0xffffffffu, mloc1, 1));
        mloc1 = fmaxf(mloc1, __shfl_xor_sync(0xffffffffu, mloc1, 2));
        float mn0 = fmaxf(m0, mloc0), mn1 = fmaxf(m1, mloc1);
        float a0 = exp2f(m0 - mn0), a1 = exp2f(m1 - mn1);
        m0 = mn0; m1 = mn1;

        float ll0 = 0.0f, ll1 = 0.0f;
        uint32_t ph[4][4], pl[4][4];
#pragma unroll
        for (int nt = 0; nt < 8; nt++) {
            float p0 = exp2f(s[nt][0] - mn0);
            float p1 = exp2f(s[nt][1] - mn0);
            float p2 = exp2f(s[nt][2] - mn1);
            float p3 = exp2f(s[nt][3] - mn1);
            ll0 += p0 + p1; ll1 += p2 + p3;
            uint32_t hA, hB;
            PACK_BF16X2(hA, p0, p1);
            PACK_BF16X2(hB, p2, p3);
            float r0 = p0 - __uint_as_float(hA << 16);
            float r1 = p1 - __uint_as_float(hA & 0xFFFF0000u);
            float r2 = p2 - __uint_as_float(hB << 16);
            float r3 = p3 - __uint_as_float(hB & 0xFFFF0000u);
            uint32_t lA, lB;
            PACK_BF16X2(lA, r0, r1);
            PACK_BF16X2(lB, r2, r3);
            const int kp = nt >> 1, hi8 = (nt & 1) * 2;
            ph[kp][hi8] = hA; ph[kp][hi8 + 1] = hB;
            pl[kp][hi8] = lA; pl[kp][hi8 + 1] = lB;
        }
        ll0 += __shfl_xor_sync(0xffffffffu, ll0, 1);
        ll0 += __shfl_xor_sync(0xffffffffu, ll0, 2);
        ll1 += __shfl_xor_sync(0xffffffffu, ll1, 1);
        ll1 += __shfl_xor_sync(0xffffffffu, ll1, 2);
        l0 = l0 * a0 + ll0;
        l1 = l1 * a1 + ll1;
#pragma unroll
        for (int nt = 0; nt < 16; nt++) {
            o[nt][0] *= a0; o[nt][1] *= a0;
            o[nt][2] *= a1; o[nt][3] *= a1;
        }

#pragma unroll
        for (int kp = 0; kp < 4; kp++) {
            const int vrow = kp * 16 + (lane & 7) + ((lane >> 3) & 1) * 8;
#pragma unroll
            for (int nt2 = 0; nt2 < 8; nt2++) {
                uint32_t vh[4], vl[4];
                const int vcol = nt2 * 16 + (lane >> 4) * 8;
                uint32_t vaddr = st + T_VH + vrow * RSTR + vcol * 2;
                LDSM_X4_T(vh[0], vh[1], vh[2], vh[3], vaddr);
                LDSM_X4_T(vl[0], vl[1], vl[2], vl[3], vaddr + (T_VL - T_VH));
                MMA16816(o[2 * nt2],     ph[kp], &vh[0]);
                MMA16816(o[2 * nt2 + 1], ph[kp], &vh[2]);
                MMA16816(o[2 * nt2],     ph[kp], &vl[0]);
                MMA16816(o[2 * nt2 + 1], ph[kp], &vl[2]);
                MMA16816(o[2 * nt2],     pl[kp], &vh[0]);
                MMA16816(o[2 * nt2 + 1], pl[kp], &vh[2]);
            }
        }
        __syncthreads();
    }

    const float inv0 = 1.0f / l0, inv1 = 1.0f / l1;
    const int row0 = q0 + wid * 16 + (lane >> 2);
#pragma unroll
    for (int nt = 0; nt < 16; nt++) {
        const int col = nt * 8 + (lane & 3) * 2;
        const size_t idx0 = ((size_t)row0 * HDIM + h * HD + col) >> 1;
        const size_t idx1 = ((size_t)(row0 + 8) * HDIM + h * HD + col) >> 1;
        float f0 = o[nt][0] * inv0, f1 = o[nt][1] * inv0;
        float f2 = o[nt][2] * inv1, f3 = o[nt][3] * inv1;
        uint32_t h0, h1, l0w, l1w;
        PACK_BF16X2(h0, f0, f1);
        PACK_BF16X2(h1, f2, f3);
        float r0 = f0 - __uint_as_float(h0 << 16);
        float r1 = f1 - __uint_as_float(h0 & 0xFFFF0000u);
        float r2 = f2 - __uint_as_float(h1 << 16);
        float r3 = f3 - __uint_as_float(h1 & 0xFFFF0000u);
        PACK_BF16X2(l0w, r0, r1);
        PACK_BF16X2(l1w, r2, r3);
        ((uint32_t*)OHi)[idx0] = h0;
        ((uint32_t*)OLo)[idx0] = l0w;
        ((uint32_t*)OHi)[idx1] = h1;
        ((uint32_t*)OLo)[idx1] = l1w;
    }
}

// ---------------------------------------------------------------------------
// Launch
// ---------------------------------------------------------------------------
extern "C" void kernel_launch(void* const* d_in, const int* in_sizes, int n_in,
                              void* d_out, int out_size)
{
    (void)in_sizes; (void)n_in; (void)out_size;
    const float* hidden = (const float*)d_in[0];
    const float* target = (const float*)d_in[1];
    const float* cosb   = (const float*)d_in[2];
    const float* sinb   = (const float*)d_in[3];
    float* out = (float*)d_out;

    float *Qp, *Kp;
    cudaGetSymbolAddress((void**)&Qp, g_Q);
    cudaGetSymbolAddress((void**)&Kp, g_K);

    __nv_bfloat16 *hidHi, *hidLo, *tgtHi, *tgtLo, *WqHi, *WqLo, *WkHi, *WkLo,
                  *WvHi, *WvLo, *WoHi, *WoLo, *AHi, *ALo,
                  *Qhp, *Qlp, *Khp, *Klp;
    cudaGetSymbolAddress((void**)&hidHi, g_hidHi);
    cudaGetSymbolAddress((void**)&hidLo, g_hidLo);
    cudaGetSymbolAddress((void**)&tgtHi, g_tgtHi);
    cudaGetSymbolAddress((void**)&tgtLo, g_tgtLo);
    cudaGetSymbolAddress((void**)&WqHi, g_WqHi);
    cudaGetSymbolAddress((void**)&WqLo, g_WqLo);
    cudaGetSymbolAddress((void**)&WkHi, g_WkHi);
    cudaGetSymbolAddress((void**)&WkLo, g_WkLo);
    cudaGetSymbolAddress((void**)&WvHi, g_WvHi);
    cudaGetSymbolAddress((void**)&WvLo, g_WvLo);
    cudaGetSymbolAddress((void**)&WoHi, g_WoHi);
    cudaGetSymbolAddress((void**)&WoLo, g_WoLo);
    cudaGetSymbolAddress((void**)&AHi, g_AHi);
    cudaGetSymbolAddress((void**)&ALo, g_ALo);
    cudaGetSymbolAddress((void**)&Qhp, g_Qh);
    cudaGetSymbolAddress((void**)&Qlp, g_Ql);
    cudaGetSymbolAddress((void**)&Khp, g_Kh);
    cudaGetSymbolAddress((void**)&Klp, g_Kl);

    cudaFuncSetAttribute(gemm_qkv, cudaFuncAttributeMaxDynamicSharedMemorySize, SMEM_G);
    cudaFuncSetAttribute(gemm_out, cudaFuncAttributeMaxDynamicSharedMemorySize, SMEM_G);
    cudaFuncSetAttribute(attn_mma, cudaFuncAttributeMaxDynamicSharedMemorySize, ATTN_SMEM);

    // fp32 -> bf16 hi/lo splits
    {
        int n;
        n = QL * HDIM;
        cvt_split<<<n / 4 / 256, 256>>>((const float4*)hidden, (__nv_bfloat162*)hidHi, (__nv_bfloat162*)hidLo, n / 4);
        n = CTX * HDIM;
        cvt_split<<<n / 4 / 256, 256>>>((const float4*)target, (__nv_bfloat162*)tgtHi, (__nv_bfloat162*)tgtLo, n / 4);
        n = HDIM * HDIM;
        cvt_split<<<n / 4 / 256, 256>>>((const float4*)d_in[4], (__nv_bfloat162*)WqHi, (__nv_bfloat162*)WqLo, n / 4);
        n = NKV * HD * HDIM;
        cvt_split<<<n / 4 / 256, 256>>>((const float4*)d_in[5], (__nv_bfloat162*)WkHi, (__nv_bfloat162*)WkLo, n / 4);
        cvt_split<<<n / 4 / 256, 256>>>((const float4*)d_in[6], (__nv_bfloat162*)WvHi, (__nv_bfloat162*)WvLo, n / 4);
        n = HDIM * HDIM;
        cvt_split<<<n / 4 / 256, 256>>>((const float4*)d_in[7], (__nv_bfloat162*)WoHi, (__nv_bfloat162*)WoLo, n / 4);
    }

    // All input projections in one launch (512 CTAs)
    gemm_qkv<<<512, 512, SMEM_G>>>(Qp, Kp);

    // RoPE + splits for attention operands (V already split by gemm epilogue)
    rope_q_split<<<(QL * NH * 64) / 256, 256>>>(Qp, cosb, sinb, Qhp, Qlp);
    rope_k_split<<<(NKV * KVLEN * 64) / 256, 256>>>(Kp, cosb, sinb, Khp, Klp);

    // Flash attention (HMMA, 3-pass split); writes bf16 hi/lo for Wo
    attn_mma<<<dim3(QL / BQ, NH), 256, ATTN_SMEM>>>(Qhp, Qlp, AHi, ALo);

    // Output projection
    gemm_out<<<dim3(HDIM / TN, QL / TM), 512, SMEM_G>>>(out);
}

// round 10
// speedup vs baseline: 1.5267x; 1.5267x over previous
#include <cuda_runtime.h>
#include <cuda_bf16.h>
#include <math.h>
#include <stdint.h>

// Problem dims
#define QL 2048
#define CTX 2048
#define HDIM 4096
#define NH 32
#define NKV 8
#define HD 128
#define KVLEN (CTX + QL)          // 4096
#define KVSTRIDE (KVLEN * HD)     // elements per kv head

#define QSCALE (0.08838834764831845f * 1.4426950408889634f)   // (1/sqrt(128))*log2(e)

// ---------------------------------------------------------------------------
// Scratch (__device__ globals; allocation-free rule)
// ---------------------------------------------------------------------------
__device__ float g_Q[(size_t)QL * HDIM];
__device__ float g_K[(size_t)NKV * KVLEN * HD];

__device__ __nv_bfloat16 g_hidHi[(size_t)QL * HDIM],  g_hidLo[(size_t)QL * HDIM];
__device__ __nv_bfloat16 g_tgtHi[(size_t)CTX * HDIM], g_tgtLo[(size_t)CTX * HDIM];
__device__ __nv_bfloat16 g_WqHi[(size_t)HDIM * HDIM], g_WqLo[(size_t)HDIM * HDIM];
__device__ __nv_bfloat16 g_WkHi[(size_t)NKV * HD * HDIM], g_WkLo[(size_t)NKV * HD * HDIM];
__device__ __nv_bfloat16 g_WvHi[(size_t)NKV * HD * HDIM], g_WvLo[(size_t)NKV * HD * HDIM];
__device__ __nv_bfloat16 g_WoHi[(size_t)HDIM * HDIM], g_WoLo[(size_t)HDIM * HDIM];
__device__ __nv_bfloat16 g_AHi[(size_t)QL * HDIM],  g_ALo[(size_t)QL * HDIM];

__device__ __nv_bfloat16 g_Qh[(size_t)QL * HDIM],  g_Ql[(size_t)QL * HDIM];
__device__ __nv_bfloat16 g_Kh[(size_t)NKV * KVLEN * HD], g_Kl[(size_t)NKV * KVLEN * HD];
__device__ __nv_bfloat16 g_Vh[(size_t)NKV * KVLEN * HD], g_Vl[(size_t)NKV * KVLEN * HD];

// ---------------------------------------------------------------------------
// PTX helpers (base sm_103-legal only: cp.async, ldmatrix, mma.sync)
// ---------------------------------------------------------------------------
__device__ __forceinline__ uint32_t smem_u32(const void* p) {
    uint32_t a;
    asm("{ .reg .u64 t; cvta.to.shared.u64 t, %1; cvt.u32.u64 %0, t; }" : "=r"(a) : "l"(p));
    return a;
}
#define CP_ASYNC16(dst, src) \
    asm volatile("cp.async.cg.shared.global [%0], [%1], 16;" :: "r"(dst), "l"(src))
#define CP_COMMIT() asm volatile("cp.async.commit_group;" ::: "memory")
#define CP_WAIT1()  asm volatile("cp.async.wait_group 1;" ::: "memory")

#define LDSM_X4(r0, r1, r2, r3, addr) \
    asm volatile("ldmatrix.sync.aligned.m8n8.x4.shared.b16 {%0,%1,%2,%3}, [%4];" \
                 : "=r"(r0), "=r"(r1), "=r"(r2), "=r"(r3) : "r"(addr))
#define LDSM_X4_T(r0, r1, r2, r3, addr) \
    asm volatile("ldmatrix.sync.aligned.m8n8.x4.trans.shared.b16 {%0,%1,%2,%3}, [%4];" \
                 : "=r"(r0), "=r"(r1), "=r"(r2), "=r"(r3) : "r"(addr))

#define MMA16816(d, a, b) \
    asm volatile("mma.sync.aligned.m16n8k16.row.col.f32.bf16.bf16.f32 " \
                 "{%0,%1,%2,%3}, {%4,%5,%6,%7}, {%8,%9}, {%0,%1,%2,%3};" \
                 : "+f"((d)[0]), "+f"((d)[1]), "+f"((d)[2]), "+f"((d)[3]) \
                 : "r"((a)[0]), "r"((a)[1]), "r"((a)[2]), "r"((a)[3]), \
                   "r"((b)[0]), "r"((b)[1]))

#define PACK_BF16X2(r, flo, fhi) \
    asm("cvt.rn.bf16x2.f32 %0, %1, %2;" : "=r"(r) : "f"(fhi), "f"(flo))

// ---------------------------------------------------------------------------
// bf16-split HMMA GEMM (R6 config: 128x256 CTA tile, 256 threads, warp 64x64,
// K-chunk 32, 3-stage cp.async pipeline).
// mode 0: C row-major [., ldn]
// mode 1: KV fp32 layout C[head][pos0+row][hd]
// mode 2: V bf16 hi/lo split directly to g_Vh/g_Vl
// ---------------------------------------------------------------------------
#define TM 128
#define TN 256
#define TK 32
#define A_TILE_B (128 * 80)               // 10240 (80B row stride)
#define B_TILE_B (256 * 80)               // 20480
#define OFF_ALO A_TILE_B
#define OFF_BHI (2 * A_TILE_B)
#define OFF_BLO (2 * A_TILE_B + B_TILE_B)
#define STG_B (2 * A_TILE_B + 2 * B_TILE_B)   // 61440
#define SMEM_G (3 * STG_B)                // 184320

__device__ __forceinline__ void g_load_stage(
    uint32_t sb, int stage, int tid,
    const __nv_bfloat16* aHi, const __nv_bfloat16* aLo,
    const __nv_bfloat16* bHi, const __nv_bfloat16* bLo,
    int bm, int bn, int K, int k0)
{
    const uint32_t st = sb + stage * STG_B;
#pragma unroll
    for (int t = 0; t < 12; t++) {
        int idx = tid + 256 * t;          // 0..3071
        const __nv_bfloat16* base;
        int grow, r;
        uint32_t toff;
        if (idx < 512)       { base = aHi; r = idx >> 2;           grow = bm + r; toff = 0; }
        else if (idx < 1024) { base = aLo; r = (idx - 512) >> 2;   grow = bm + r; toff = OFF_ALO; }
        else if (idx < 2048) { base = bHi; r = (idx - 1024) >> 2;  grow = bn + r; toff = OFF_BHI; }
        else                 { base = bLo; r = (idx - 2048) >> 2;  grow = bn + r; toff = OFF_BLO; }
        int c = idx & 3;
        const char* src = (const char*)(base + (size_t)grow * K + k0 + c * 8);
        uint32_t dst = st + toff + r * 80 + c * 16;
        CP_ASYNC16(dst, src);
    }
}

__device__ __forceinline__ void gemm_core(
    const __nv_bfloat16* __restrict__ aHi, const __nv_bfloat16* __restrict__ aLo,
    const __nv_bfloat16* __restrict__ bHi, const __nv_bfloat16* __restrict__ bLo,
    int bm, int bn, int K,
    float* __restrict__ C, int ldn, int mode, int pos0)
{
    extern __shared__ char smem[];
    const uint32_t sb = smem_u32(smem);
    const int tid = threadIdx.x;
    const int wid = tid >> 5;
    const int lane = tid & 31;
    const int wm = (wid >> 2) * 64;
    const int wn = (wid & 3) * 64;
    const int nch = K / TK;

    float acc[4][8][4];
#pragma unroll
    for (int mt = 0; mt < 4; mt++)
#pragma unroll
        for (int nt = 0; nt < 8; nt++)
#pragma unroll
            for (int i = 0; i < 4; i++) acc[mt][nt][i] = 0.0f;

    g_load_stage(sb, 0, tid, aHi, aLo, bHi, bLo, bm, bn, K, 0);
    CP_COMMIT();
    g_load_stage(sb, 1, tid, aHi, aLo, bHi, bLo, bm, bn, K, TK);
    CP_COMMIT();

    int stage = 0;
    for (int c = 0; c < nch; c++) {
        CP_WAIT1();
        __syncthreads();
        if (c + 2 < nch) {
            int s2 = stage + 2; if (s2 >= 3) s2 -= 3;
            g_load_stage(sb, s2, tid, aHi, aLo, bHi, bLo, bm, bn, K, (c + 2) * TK);
        }
        CP_COMMIT();

        const uint32_t st = sb + stage * STG_B;
#pragma unroll
        for (int kg = 0; kg < 2; kg++) {
            uint32_t ah[4][4], al[4][4];
            const int acol = kg * 16 + (lane >> 4) * 8;
#pragma unroll
            for (int mt = 0; mt < 4; mt++) {
                int row = wm + mt * 16 + (lane & 15);
                uint32_t ad = st + row * 80 + acol * 2;
                LDSM_X4(ah[mt][0], ah[mt][1], ah[mt][2], ah[mt][3], ad);
                LDSM_X4(al[mt][0], al[mt][1], al[mt][2], al[mt][3], ad + OFF_ALO);
            }
            const int bcol = kg * 16 + ((lane >> 3) & 1) * 8;
#pragma unroll
            for (int p = 0; p < 4; p++) {
                uint32_t bh[4], bl[4];
                const int brow = wn + p * 16 + (lane & 7) + (lane >> 4) * 8;
                uint32_t bd = st + OFF_BHI + brow * 80 + bcol * 2;
                LDSM_X4(bh[0], bh[1], bh[2], bh[3], bd);
                LDSM_X4(bl[0], bl[1], bl[2], bl[3], bd + (OFF_BLO - OFF_BHI));
#pragma unroll
                for (int mt = 0; mt < 4; mt++) {
                    MMA16816(acc[mt][2 * p],     ah[mt], &bh[0]);
                    MMA16816(acc[mt][2 * p + 1], ah[mt], &bh[2]);
                    MMA16816(acc[mt][2 * p],     ah[mt], &bl[0]);
                    MMA16816(acc[mt][2 * p + 1], ah[mt], &bl[2]);
                    MMA16816(acc[mt][2 * p],     al[mt], &bh[0]);
                    MMA16816(acc[mt][2 * p + 1], al[mt], &bh[2]);
                }
            }
        }
        stage++; if (stage >= 3) stage = 0;
        __syncthreads();
    }

#pragma unroll
    for (int mt = 0; mt < 4; mt++)
#pragma unroll
        for (int nt = 0; nt < 8; nt++) {
            int row = bm + wm + mt * 16 + (lane >> 2);
            int col = bn + wn + nt * 8 + (lane & 3) * 2;
            if (mode == 0) {
                *(float2*)(C + (size_t)row * ldn + col) =
                    make_float2(acc[mt][nt][0], acc[mt][nt][1]);
                *(float2*)(C + (size_t)(row + 8) * ldn + col) =
                    make_float2(acc[mt][nt][2], acc[mt][nt][3]);
            } else if (mode == 1) {
                const int head = col >> 7;
                const int hd = col & 127;
                float* base = C + (size_t)head * KVSTRIDE + hd;
                *(float2*)(base + (size_t)(pos0 + row) * HD) =
                    make_float2(acc[mt][nt][0], acc[mt][nt][1]);
                *(float2*)(base + (size_t)(pos0 + row + 8) * HD) =
                    make_float2(acc[mt][nt][2], acc[mt][nt][3]);
            } else {
                const int head = col >> 7;
                const int hd = col & 127;
                const size_t e0 = (size_t)head * KVSTRIDE + (size_t)(pos0 + row) * HD + hd;
                const size_t e1 = (size_t)head * KVSTRIDE + (size_t)(pos0 + row + 8) * HD + hd;
                float f0 = acc[mt][nt][0], f1 = acc[mt][nt][1];
                float f2 = acc[mt][nt][2], f3 = acc[mt][nt][3];
                uint32_t h0, h1, l0, l1;
                PACK_BF16X2(h0, f0, f1);
                PACK_BF16X2(h1, f2, f3);
                float r0 = f0 - __uint_as_float(h0 << 16);
                float r1 = f1 - __uint_as_float(h0 & 0xFFFF0000u);
                float r2 = f2 - __uint_as_float(h1 << 16);
                float r3 = f3 - __uint_as_float(h1 & 0xFFFF0000u);
                PACK_BF16X2(l0, r0, r1);
                PACK_BF16X2(l1, r2, r3);
                ((uint32_t*)g_Vh)[e0 >> 1] = h0;
                ((uint32_t*)g_Vl)[e0 >> 1] = l0;
                ((uint32_t*)g_Vh)[e1 >> 1] = h1;
                ((uint32_t*)g_Vl)[e1 >> 1] = l1;
            }
        }
}

// Fused Q + K(ctx,noise) + V(ctx,noise) projections: 512 CTAs, 256 threads.
__global__ __launch_bounds__(256, 1)
void gemm_qkv(float* __restrict__ Qo, float* __restrict__ Ko)
{
    const int cta = blockIdx.x;
    if (cta < 256) {
        const int bm = (cta >> 4) * TM;
        const int bn = (cta & 15) * TN;
        gemm_core(g_hidHi, g_hidLo, g_WqHi, g_WqLo, bm, bn, HDIM, Qo, HDIM, 0, 0);
    } else {
        const int r = cta - 256;
        const int z = r >> 6;
        const int bm = ((r >> 2) & 15) * TM;
        const int bn = (r & 3) * TN;
        const __nv_bfloat16 *aHi, *aLo;
        int pos0;
        if (z >> 1) { aHi = g_hidHi; aLo = g_hidLo; pos0 = CTX; }
        else        { aHi = g_tgtHi; aLo = g_tgtLo; pos0 = 0; }
        if (z & 1) {
            gemm_core(aHi, aLo, g_WvHi, g_WvLo, bm, bn, HDIM, nullptr, 0, 2, pos0);
        } else {
            gemm_core(aHi, aLo, g_WkHi, g_WkLo, bm, bn, HDIM, Ko, 0, 1, pos0);
        }
    }
}

// Output projection
__global__ __launch_bounds__(256, 1)
void gemm_out(float* __restrict__ C)
{
    const int bm = blockIdx.y * TM;
    const int bn = blockIdx.x * TN;
    gemm_core(g_AHi, g_ALo, g_WoHi, g_WoLo, bm, bn, HDIM, C, HDIM, 0, 0);
}

// ---------------------------------------------------------------------------
// fp32 -> (bf16 hi, bf16 lo) split
// ---------------------------------------------------------------------------
__global__ void cvt_split(const float4* __restrict__ x,
                          __nv_bfloat162* __restrict__ hi,
                          __nv_bfloat162* __restrict__ lo, int n4)
{
    int i = blockIdx.x * blockDim.x + threadIdx.x;
    if (i >= n4) return;
    float4 v = x[i];
    __nv_bfloat16 hx = __float2bfloat16_rn(v.x);
    __nv_bfloat16 hy = __float2bfloat16_rn(v.y);
    __nv_bfloat16 hz = __float2bfloat16_rn(v.z);
    __nv_bfloat16 hw = __float2bfloat16_rn(v.w);
    __nv_bfloat16 lx = __float2bfloat16_rn(v.x - __bfloat162float(hx));
    __nv_bfloat16 ly = __float2bfloat16_rn(v.y - __bfloat162float(hy));
    __nv_bfloat16 lz = __float2bfloat16_rn(v.z - __bfloat162float(hz));
    __nv_bfloat16 lw = __float2bfloat16_rn(v.w - __bfloat162float(hw));
    hi[2 * i + 0] = __halves2bfloat162(hx, hy);
    hi[2 * i + 1] = __halves2bfloat162(hz, hw);
    lo[2 * i + 0] = __halves2bfloat162(lx, ly);
    lo[2 * i + 1] = __halves2bfloat162(lz, lw);
}

// ---------------------------------------------------------------------------
// RoPE -> bf16 hi/lo split outputs (Q folds in scale*log2e)
// ---------------------------------------------------------------------------
__global__ void rope_q_split(const float* __restrict__ Q,
                             const float* __restrict__ cosb,
                             const float* __restrict__ sinb,
                             __nv_bfloat16* __restrict__ qh,
                             __nv_bfloat16* __restrict__ ql)
{
    int idx = blockIdx.x * blockDim.x + threadIdx.x;
    int hd = idx & 63;
    int t  = idx >> 6;
    int h  = t & (NH - 1);
    int s  = t >> 5;
    int pos = CTX + s;
    float c1 = cosb[(size_t)pos * HD + hd];
    float s1 = sinb[(size_t)pos * HD + hd];
    float c2 = cosb[(size_t)pos * HD + hd + 64];
    float s2 = sinb[(size_t)pos * HD + hd + 64];
    const float* p = Q + (size_t)s * HDIM + h * HD;
    float x1 = p[hd];
    float x2 = p[hd + 64];
    float y1 = (x1 * c1 - x2 * s1) * QSCALE;
    float y2 = (x2 * c2 + x1 * s2) * QSCALE;
    size_t o1 = (size_t)s * HDIM + h * HD + hd;
    __nv_bfloat16 h1 = __float2bfloat16_rn(y1);
    __nv_bfloat16 h2 = __float2bfloat16_rn(y2);
    qh[o1]      = h1;  ql[o1]      = __float2bfloat16_rn(y1 - __bfloat162float(h1));
    qh[o1 + 64] = h2;  ql[o1 + 64] = __float2bfloat16_rn(y2 - __bfloat162float(h2));
}

__global__ void rope_k_split(const float* __restrict__ Kb,
                             const float* __restrict__ cosb,
                             const float* __restrict__ sinb,
                             __nv_bfloat16* __restrict__ kh,
                             __nv_bfloat16* __restrict__ kl)
{
    int idx = blockIdx.x * blockDim.x + threadIdx.x;
    int hd = idx & 63;
    int t  = idx >> 6;
    int pos = t & (KVLEN - 1);
    int kvh = t >> 12;
    float c1 = cosb[(size_t)pos * HD + hd];
    float s1 = sinb[(size_t)pos * HD + hd];
    float c2 = cosb[(size_t)pos * HD + hd + 64];
    float s2 = sinb[(size_t)pos * HD + hd + 64];
    const float* p = Kb + (size_t)kvh * KVSTRIDE + (size_t)pos * HD;
    float x1 = p[hd];
    float x2 = p[hd + 64];
    float y1 = x1 * c1 - x2 * s1;
    float y2 = x2 * c2 + x1 * s2;
    size_t o1 = (size_t)kvh * KVSTRIDE + (size_t)pos * HD + hd;
    __nv_bfloat16 h1 = __float2bfloat16_rn(y1);
    __nv_bfloat16 h2 = __float2bfloat16_rn(y2);
    kh[o1]      = h1;  kl[o1]      = __float2bfloat16_rn(y1 - __bfloat162float(h1));
    kh[o1 + 64] = h2;  kl[o1 + 64] = __float2bfloat16_rn(y2 - __bfloat162float(h2));
}

// ---------------------------------------------------------------------------
// Tensor-core flash attention (bf16 3-pass split, mma.sync) — passing version
// ---------------------------------------------------------------------------
#define BQ 128
#define BKV 64
#define RSTR 272
#define SQ_L 34816
#define SSTG 69632
#define STG_SZ 69632
#define T_KH 0
#define T_KL 17408
#define T_VH 34816
#define T_VL 52224
#define ATTN_SMEM (SSTG + 2 * STG_SZ)

__device__ __forceinline__ void attn_load_kv(
    uint32_t sb, int stage, int tid, int kvh, int kc)
{
    const uint32_t st = sb + SSTG + stage * STG_SZ;
    const size_t base = (size_t)kvh * KVSTRIDE + (size_t)kc * BKV * HD;
    const __nv_bfloat16* srcs[4] = { g_Kh + base, g_Kl + base, g_Vh + base, g_Vl + base };
#pragma unroll
    for (int t = 0; t < 16; t++) {
        int idx = tid + 256 * t;
        int tile = idx >> 10;
        int rem = idx & 1023;
        int r = rem >> 4;
        int c = rem & 15;
        const char* src = (const char*)(srcs[tile] + (size_t)r * HD) + c * 16;
        uint32_t dst = st + tile * 17408 + r * RSTR + c * 16;
        CP_ASYNC16(dst, src);
    }
}

__global__ __launch_bounds__(256, 1)
void attn_mma(const __nv_bfloat16* __restrict__ Qh, const __nv_bfloat16* __restrict__ Ql,
              __nv_bfloat16* __restrict__ OHi, __nv_bfloat16* __restrict__ OLo)
{
    extern __shared__ char smem[];
    const uint32_t sb = smem_u32(smem);
    const int tid = threadIdx.x;
    const int wid = tid >> 5;
    const int lane = tid & 31;
    const int h  = blockIdx.y;
    const int q0 = blockIdx.x * BQ;
    const int kvh = h >> 2;

#pragma unroll
    for (int t = 0; t < 16; t++) {
        int idx = tid + 256 * t;
        int tile = idx >> 11;
        int rem = idx & 2047;
        int r = rem >> 4;
        int c = rem & 15;
        const __nv_bfloat16* base = tile ? Ql : Qh;
        const char* src = (const char*)(base + (size_t)(q0 + r) * HDIM + h * HD) + c * 16;
        uint32_t dst = sb + tile * 34816 + r * RSTR + c * 16;
        CP_ASYNC16(dst, src);
    }
    CP_COMMIT();
    attn_load_kv(sb, 0, tid, kvh, 0);
    CP_COMMIT();

    float o[16][4];
#pragma unroll
    for (int nt = 0; nt < 16; nt++)
#pragma unroll
        for (int i = 0; i < 4; i++) o[nt][i] = 0.0f;
    float m0 = -INFINITY, m1 = -INFINITY, l0 = 0.0f, l1 = 0.0f;

    const int NCH = KVLEN / BKV;
    for (int kc = 0; kc < NCH; kc++) {
        if (kc + 1 < NCH) attn_load_kv(sb, (kc + 1) & 1, tid, kvh, kc + 1);
        CP_COMMIT();
        CP_WAIT1();
        __syncthreads();

        const uint32_t st = sb + SSTG + (kc & 1) * STG_SZ;

        float s[8][4];
#pragma unroll
        for (int nt = 0; nt < 8; nt++)
#pragma unroll
            for (int i = 0; i < 4; i++) s[nt][i] = 0.0f;

#pragma unroll
        for (int d16 = 0; d16 < 8; d16++) {
            uint32_t qhf[4], qlf[4];
            const int arow = wid * 16 + (lane & 15);
            const int acol = d16 * 16 + (lane >> 4) * 8;
            uint32_t aaddr = sb + arow * RSTR + acol * 2;
            LDSM_X4(qhf[0], qhf[1], qhf[2], qhf[3], aaddr);
            LDSM_X4(qlf[0], qlf[1], qlf[2], qlf[3], aaddr + SQ_L);
            const int bcol = d16 * 16 + ((lane >> 3) & 1) * 8;
#pragma unroll
            for (int nt2 = 0; nt2 < 4; nt2++) {
                uint32_t bh[4], bl[4];
                const int brow = nt2 * 16 + (lane & 7) + (lane >> 4) * 8;
                uint32_t baddr = st + T_KH + brow * RSTR + bcol * 2;
                LDSM_X4(bh[0], bh[1], bh[2], bh[3], baddr);
                LDSM_X4(bl[0], bl[1], bl[2], bl[3], baddr + (T_KL - T_KH));
                MMA16816(s[2 * nt2],     qhf, &bh[0]);
                MMA16816(s[2 * nt2 + 1], qhf, &bh[2]);
                MMA16816(s[2 * nt2],     qhf, &bl[0]);
                MMA16816(s[2 * nt2 + 1], qhf, &bl[2]);
                MMA16816(s[2 * nt2],     qlf, &bh[0]);
                MMA16816(s[2 * nt2 + 1], qlf, &bh[2]);
            }
        }

        float mloc0 = -INFINITY, mloc1 = -INFINITY;
#pragma unroll
        for (int nt = 0; nt < 8; nt++) {
            mloc0 = fmaxf(mloc0, fmaxf(s[nt][0], s[nt][1]));
            mloc1 = fmaxf(mloc1, fmaxf(s[nt][2], s[nt][3]));
        }
        mloc0 = fmaxf(mloc0, __shfl_xor_sync(0xffffffffu, mloc0, 1));
        mloc0 = fmaxf(mloc0, __shfl_xor_sync(0xffffffffu, mloc0, 2));
        mloc1 = fmaxf(mloc1, __shfl_xor_sync(0xffffffffu, mloc1, 1));
        mloc1 = fmaxf(mloc1, __shfl_xor_sync(0xffffffffu, mloc1, 2));
        float mn0 = fmaxf(m0, mloc0), mn1 = fmaxf(m1, mloc1);
        float a0 = exp2f(m0 - mn0), a1 = exp2f(m1 - mn1);
        m0 = mn0; m1 = mn1;

        float ll0 = 0.0f, ll1 = 0.0f;
        uint32_t ph[4][4], pl[4][4];
#pragma unroll
        for (int nt = 0; nt < 8; nt++) {
            float p0 = exp2f(s[nt][0] - mn0);
            float p1 = exp2f(s[nt][1] - mn0);
            float p2 = exp2f(s[nt][2] - mn1);
            float p3 = exp2f(s[nt][3] - mn1);
            ll0 += p0 + p1; ll1 += p2 + p3;
            uint32_t hA, hB;
            PACK_BF16X2(hA, p0, p1);
            PACK_BF16X2(hB, p2, p3);
            float r0 = p0 - __uint_as_float(hA << 16);
            float r1 = p1 - __uint_as_float(hA & 0xFFFF0000u);
            float r2 = p2 - __uint_as_float(hB << 16);
            float r3 = p3 - __uint_as_float(hB & 0xFFFF0000u);
            uint32_t lA, lB;
            PACK_BF16X2(lA, r0, r1);
            PACK_BF16X2(lB, r2, r3);
            const int kp = nt >> 1, hi8 = (nt & 1) * 2;
            ph[kp][hi8] = hA; ph[kp][hi8 + 1] = hB;
            pl[kp][hi8] = lA; pl[kp][hi8 + 1] = lB;
        }
        ll0 += __shfl_xor_sync(0xffffffffu, ll0, 1);
        ll0 += __shfl_xor_sync(0xffffffffu, ll0, 2);
        ll1 += __shfl_xor_sync(0xffffffffu, ll1, 1);
        ll1 += __shfl_xor_sync(0xffffffffu, ll1, 2);
        l0 = l0 * a0 + ll0;
        l1 = l1 * a1 + ll1;
#pragma unroll
        for (int nt = 0; nt < 16; nt++) {
            o[nt][0] *= a0; o[nt][1] *= a0;
            o[nt][2] *= a1; o[nt][3] *= a1;
        }

#pragma unroll
        for (int kp = 0; kp < 4; kp++) {
            const int vrow = kp * 16 + (lane & 7) + ((lane >> 3) & 1) * 8;
#pragma unroll
            for (int nt2 = 0; nt2 < 8; nt2++) {
                uint32_t vh[4], vl[4];
                const int vcol = nt2 * 16 + (lane >> 4) * 8;
                uint32_t vaddr = st + T_VH + vrow * RSTR + vcol * 2;
                LDSM_X4_T(vh[0], vh[1], vh[2], vh[3], vaddr);
                LDSM_X4_T(vl[0], vl[1], vl[2], vl[3], vaddr + (T_VL - T_VH));
                MMA16816(o[2 * nt2],     ph[kp], &vh[0]);
                MMA16816(o[2 * nt2 + 1], ph[kp], &vh[2]);
                MMA16816(o[2 * nt2],     ph[kp], &vl[0]);
                MMA16816(o[2 * nt2 + 1], ph[kp], &vl[2]);
                MMA16816(o[2 * nt2],     pl[kp], &vh[0]);
                MMA16816(o[2 * nt2 + 1], pl[kp], &vh[2]);
            }
        }
        __syncthreads();
    }

    const float inv0 = 1.0f / l0, inv1 = 1.0f / l1;
    const int row0 = q0 + wid * 16 + (lane >> 2);
#pragma unroll
    for (int nt = 0; nt < 16; nt++) {
        const int col = nt * 8 + (lane & 3) * 2;
        const size_t idx0 = ((size_t)row0 * HDIM + h * HD + col) >> 1;
        const size_t idx1 = ((size_t)(row0 + 8) * HDIM + h * HD + col) >> 1;
        float f0 = o[nt][0] * inv0, f1 = o[nt][1] * inv0;
        float f2 = o[nt][2] * inv1, f3 = o[nt][3] * inv1;
        uint32_t h0, h1, l0w, l1w;
        PACK_BF16X2(h0, f0, f1);
        PACK_BF16X2(h1, f2, f3);
        float r0 = f0 - __uint_as_float(h0 << 16);
        float r1 = f1 - __uint_as_float(h0 & 0xFFFF0000u);
        float r2 = f2 - __uint_as_float(h1 << 16);
        float r3 = f3 - __uint_as_float(h1 & 0xFFFF0000u);
        PACK_BF16X2(l0w, r0, r1);
        PACK_BF16X2(l1w, r2, r3);
        ((uint32_t*)OHi)[idx0] = h0;
        ((uint32_t*)OLo)[idx0] = l0w;
        ((uint32_t*)OHi)[idx1] = h1;
        ((uint32_t*)OLo)[idx1] = l1w;
    }
}

// ---------------------------------------------------------------------------
// Launch
// ---------------------------------------------------------------------------
extern "C" void kernel_launch(void* const* d_in, const int* in_sizes, int n_in,
                              void* d_out, int out_size)
{
    (void)in_sizes; (void)n_in; (void)out_size;
    const float* hidden = (const float*)d_in[0];
    const float* target = (const float*)d_in[1];
    const float* cosb   = (const float*)d_in[2];
    const float* sinb   = (const float*)d_in[3];
    float* out = (float*)d_out;

    float *Qp, *Kp;
    cudaGetSymbolAddress((void**)&Qp, g_Q);
    cudaGetSymbolAddress((void**)&Kp, g_K);

    __nv_bfloat16 *hidHi, *hidLo, *tgtHi, *tgtLo, *WqHi, *WqLo, *WkHi, *WkLo,
                  *WvHi, *WvLo, *WoHi, *WoLo, *AHi, *ALo,
                  *Qhp, *Qlp, *Khp, *Klp;
    cudaGetSymbolAddress((void**)&hidHi, g_hidHi);
    cudaGetSymbolAddress((void**)&hidLo, g_hidLo);
    cudaGetSymbolAddress((void**)&tgtHi, g_tgtHi);
    cudaGetSymbolAddress((void**)&tgtLo, g_tgtLo);
    cudaGetSymbolAddress((void**)&WqHi, g_WqHi);
    cudaGetSymbolAddress((void**)&WqLo, g_WqLo);
    cudaGetSymbolAddress((void**)&WkHi, g_WkHi);
    cudaGetSymbolAddress((void**)&WkLo, g_WkLo);
    cudaGetSymbolAddress((void**)&WvHi, g_WvHi);
    cudaGetSymbolAddress((void**)&WvLo, g_WvLo);
    cudaGetSymbolAddress((void**)&WoHi, g_WoHi);
    cudaGetSymbolAddress((void**)&WoLo, g_WoLo);
    cudaGetSymbolAddress((void**)&AHi, g_AHi);
    cudaGetSymbolAddress((void**)&ALo, g_ALo);
    cudaGetSymbolAddress((void**)&Qhp, g_Qh);
    cudaGetSymbolAddress((void**)&Qlp, g_Ql);
    cudaGetSymbolAddress((void**)&Khp, g_Kh);
    cudaGetSymbolAddress((void**)&Klp, g_Kl);

    cudaFuncSetAttribute(gemm_qkv, cudaFuncAttributeMaxDynamicSharedMemorySize, SMEM_G);
    cudaFuncSetAttribute(gemm_out, cudaFuncAttributeMaxDynamicSharedMemorySize, SMEM_G);
    cudaFuncSetAttribute(attn_mma, cudaFuncAttributeMaxDynamicSharedMemorySize, ATTN_SMEM);

    // fp32 -> bf16 hi/lo splits
    {
        int n;
        n = QL * HDIM;
        cvt_split<<<n / 4 / 256, 256>>>((const float4*)hidden, (__nv_bfloat162*)hidHi, (__nv_bfloat162*)hidLo, n / 4);
        n = CTX * HDIM;
        cvt_split<<<n / 4 / 256, 256>>>((const float4*)target, (__nv_bfloat162*)tgtHi, (__nv_bfloat162*)tgtLo, n / 4);
        n = HDIM * HDIM;
        cvt_split<<<n / 4 / 256, 256>>>((const float4*)d_in[4], (__nv_bfloat162*)WqHi, (__nv_bfloat162*)WqLo, n / 4);
        n = NKV * HD * HDIM;
        cvt_split<<<n / 4 / 256, 256>>>((const float4*)d_in[5], (__nv_bfloat162*)WkHi, (__nv_bfloat162*)WkLo, n / 4);
        cvt_split<<<n / 4 / 256, 256>>>((const float4*)d_in[6], (__nv_bfloat162*)WvHi, (__nv_bfloat162*)WvLo, n / 4);
        n = HDIM * HDIM;
        cvt_split<<<n / 4 / 256, 256>>>((const float4*)d_in[7], (__nv_bfloat162*)WoHi, (__nv_bfloat162*)WoLo, n / 4);
    }

    // All input projections in one launch (512 CTAs, 256 threads)
    gemm_qkv<<<512, 256, SMEM_G>>>(Qp, Kp);

    // RoPE + splits for attention operands (V already split by gemm epilogue)
    rope_q_split<<<(QL * NH * 64) / 256, 256>>>(Qp, cosb, sinb, Qhp, Qlp);
    rope_k_split<<<(NKV * KVLEN * 64) / 256, 256>>>(Kp, cosb, sinb, Khp, Klp);

    // Flash attention (HMMA, 3-pass split); writes bf16 hi/lo for Wo
    attn_mma<<<dim3(QL / BQ, NH), 256, ATTN_SMEM>>>(Qhp, Qlp, AHi, ALo);

    // Output projection
    gemm_out<<<dim3(HDIM / TN, QL / TM), 256, SMEM_G>>>(out);
}